// round 2
// baseline (speedup 1.0000x reference)
#include <cuda_runtime.h>

#define NN   100000
#define FIN  256
#define CC   128
#define EE   1600000

// Scratch (allocation-free rule: __device__ globals)
__device__ float g_h[NN * CC];
__device__ float g_z[NN * CC];
__device__ int   g_deg[NN];
__device__ float g_dinv[NN];

// ---------------------------------------------------------------------------
// GEMM: out[n,c] = act( sum_k A[n,k] * W[c,k] + bias[c] )
// Tile: 64 rows x 128 cols per block, 256 threads, each thread 4x8.
// K in {128, 256}, multiple of 32.
// ---------------------------------------------------------------------------
template<int K, bool RELU, bool BIAS>
__global__ __launch_bounds__(256) void gemm_kernel(
    const float* __restrict__ A,
    const float* __restrict__ W,
    const float* __restrict__ bias,
    float* __restrict__ out,
    int n_rows)
{
    __shared__ float As[32][68];    // k-major, padded (68*4 = 272B, 16B aligned)
    __shared__ float Ws[32][132];   // k-major, padded (132*4 = 528B, 16B aligned)

    const int tid = threadIdx.x;
    const int tx  = tid & 15;       // col group: 16 groups of 8 cols
    const int ty  = tid >> 4;       // row group: 16 groups of 4 rows
    const int row0 = blockIdx.x * 64;

    float acc[4][8];
#pragma unroll
    for (int i = 0; i < 4; ++i)
#pragma unroll
        for (int j = 0; j < 8; ++j) acc[i][j] = 0.0f;

    for (int kt = 0; kt < K; kt += 32) {
        // Load A tile: 64 rows x 32 k, float4 per thread, 2 iters
#pragma unroll
        for (int it = 0; it < 2; ++it) {
            int r  = (tid >> 3) + it * 32;     // 0..63
            int k4 = (tid & 7) * 4;            // 0..28
            float4 v = make_float4(0.f, 0.f, 0.f, 0.f);
            int gr = row0 + r;
            if (gr < n_rows)
                v = *(const float4*)(A + (size_t)gr * K + kt + k4);
            As[k4 + 0][r] = v.x;
            As[k4 + 1][r] = v.y;
            As[k4 + 2][r] = v.z;
            As[k4 + 3][r] = v.w;
        }
        // Load W tile: 128 cols x 32 k, 4 iters
#pragma unroll
        for (int it = 0; it < 4; ++it) {
            int c  = (tid >> 3) + it * 32;     // 0..127
            int k4 = (tid & 7) * 4;
            float4 v = *(const float4*)(W + (size_t)c * K + kt + k4);
            Ws[k4 + 0][c] = v.x;
            Ws[k4 + 1][c] = v.y;
            Ws[k4 + 2][c] = v.z;
            Ws[k4 + 3][c] = v.w;
        }
        __syncthreads();

#pragma unroll
        for (int kk = 0; kk < 32; ++kk) {
            float4 a4 = *(const float4*)&As[kk][ty * 4];
            float4 b0 = *(const float4*)&Ws[kk][tx * 8];
            float4 b1 = *(const float4*)&Ws[kk][tx * 8 + 4];
            float a[4] = {a4.x, a4.y, a4.z, a4.w};
            float b[8] = {b0.x, b0.y, b0.z, b0.w, b1.x, b1.y, b1.z, b1.w};
#pragma unroll
            for (int i = 0; i < 4; ++i)
#pragma unroll
                for (int j = 0; j < 8; ++j)
                    acc[i][j] += a[i] * b[j];
        }
        __syncthreads();
    }

    // Epilogue
#pragma unroll
    for (int i = 0; i < 4; ++i) {
        int gr = row0 + ty * 4 + i;
        if (gr >= n_rows) continue;
        float* op = out + (size_t)gr * CC + tx * 8;
#pragma unroll
        for (int j = 0; j < 8; ++j) {
            float v = acc[i][j];
            if (BIAS) v += bias[tx * 8 + j];
            if (RELU) v = fmaxf(v, 0.0f);
            op[j] = v;
        }
    }
}

// ---------------------------------------------------------------------------
// Degree / normalization
// ---------------------------------------------------------------------------
__global__ void init_deg_kernel() {
    int i = blockIdx.x * blockDim.x + threadIdx.x;
    if (i < NN) g_deg[i] = 1;   // self loop
}

__global__ void count_deg_kernel(const int* __restrict__ dst) {
    int e = blockIdx.x * blockDim.x + threadIdx.x;
    if (e < EE) atomicAdd(&g_deg[dst[e]], 1);
}

__global__ void dinv_kernel() {
    int i = blockIdx.x * blockDim.x + threadIdx.x;
    if (i < NN) g_dinv[i] = rsqrtf((float)g_deg[i]);
}

// ---------------------------------------------------------------------------
// out = b2 + z * dinv^2 (self-loop term + bias init)
// ---------------------------------------------------------------------------
__global__ void self_init_kernel(const float* __restrict__ z,
                                 const float* __restrict__ b2,
                                 float* __restrict__ out)
{
    int idx = blockIdx.x * blockDim.x + threadIdx.x;   // over NN*CC/4
    if (idx >= NN * CC / 4) return;
    int base = idx * 4;
    int n = base / CC;
    int c = base % CC;
    float di = g_dinv[n];
    float w  = di * di;
    float4 zv = *(const float4*)(z + base);
    float4 bv = *(const float4*)(b2 + c);
    float4 o;
    o.x = bv.x + zv.x * w;
    o.y = bv.y + zv.y * w;
    o.z = bv.z + zv.z * w;
    o.w = bv.w + zv.w * w;
    *(float4*)(out + base) = o;
}

// ---------------------------------------------------------------------------
// Edge scatter: one warp per edge. out[dst] += z[src] * dinv[src]*dinv[dst]
// ---------------------------------------------------------------------------
__global__ __launch_bounds__(256) void scatter_kernel(
    const int* __restrict__ src,
    const int* __restrict__ dst,
    const float* __restrict__ z,
    float* __restrict__ out)
{
    int e = (blockIdx.x * blockDim.x + threadIdx.x) >> 5;
    if (e >= EE) return;
    int lane = threadIdx.x & 31;
    int s = src[e];
    int d = dst[e];
    float w = g_dinv[s] * g_dinv[d];
    float4 v = *(const float4*)(z + (size_t)s * CC + lane * 4);
    float* op = out + (size_t)d * CC + lane * 4;
    atomicAdd(op + 0, v.x * w);
    atomicAdd(op + 1, v.y * w);
    atomicAdd(op + 2, v.z * w);
    atomicAdd(op + 3, v.w * w);
}

// ---------------------------------------------------------------------------
extern "C" void kernel_launch(void* const* d_in, const int* in_sizes, int n_in,
                              void* d_out, int out_size)
{
    const float* x  = (const float*)d_in[0];
    const int*   ei = (const int*)  d_in[1];
    const float* W1 = (const float*)d_in[2];
    const float* b1 = (const float*)d_in[3];
    const float* W2 = (const float*)d_in[4];
    const float* b2 = (const float*)d_in[5];
    float* out = (float*)d_out;

    const int* src = ei;
    const int* dst = ei + EE;

    float* h_ptr; cudaGetSymbolAddress((void**)&h_ptr, g_h);
    float* z_ptr; cudaGetSymbolAddress((void**)&z_ptr, g_z);

    // Degree pipeline
    init_deg_kernel<<<(NN + 255) / 256, 256>>>();
    count_deg_kernel<<<(EE + 255) / 256, 256>>>(dst);
    dinv_kernel<<<(NN + 255) / 256, 256>>>();

    // h = relu(x @ W1^T + b1)
    gemm_kernel<FIN, true, true><<<(NN + 63) / 64, 256>>>(x, W1, b1, h_ptr, NN);
    // z = h @ W2^T
    gemm_kernel<CC, false, false><<<(NN + 63) / 64, 256>>>(h_ptr, W2, nullptr, z_ptr, NN);

    // out = b2 + z * dinv^2
    self_init_kernel<<<(NN * CC / 4 + 255) / 256, 256>>>(z_ptr, b2, out);

    // scatter edges
    scatter_kernel<<<(EE * 32 + 255) / 256, 256>>>(src, dst, z_ptr, out);
}

// round 3
// speedup vs baseline: 3.7753x; 3.7753x over previous
#include <cuda_runtime.h>

#define NN   100000
#define FIN  256
#define CC   128
#define EE   1600000
#define NB1  ((NN + 1023) / 1024)   // 98 scan blocks

// ---------------- scratch (__device__ globals, allocation-free rule) --------
__device__ float g_h[NN * CC];
__device__ float g_z[NN * CC];
__device__ int   g_cnt[NN];        // in-degree (edges only, no self loop)
__device__ float g_dinv[NN];
__device__ int   g_row_start[NN];  // exclusive scan of g_cnt
__device__ int   g_cursor[NN];
__device__ int   g_csr_src[EE];
__device__ int   g_bsum[NB1];

// ---------------------------------------------------------------------------
// TF32 helpers
// ---------------------------------------------------------------------------
__device__ __forceinline__ unsigned f2tf(float x) {
    unsigned r;
    asm("cvt.rna.tf32.f32 %0, %1;" : "=r"(r) : "f"(x));
    return r;
}

__device__ __forceinline__ void mma_tf32(float c[4],
                                         unsigned a0, unsigned a1, unsigned a2, unsigned a3,
                                         unsigned b0, unsigned b1) {
    asm volatile(
        "mma.sync.aligned.m16n8k8.row.col.f32.tf32.tf32.f32 "
        "{%0,%1,%2,%3}, {%4,%5,%6,%7}, {%8,%9}, {%0,%1,%2,%3};"
        : "+f"(c[0]), "+f"(c[1]), "+f"(c[2]), "+f"(c[3])
        : "r"(a0), "r"(a1), "r"(a2), "r"(a3), "r"(b0), "r"(b1));
}

// ---------------------------------------------------------------------------
// TF32 GEMM: out[n,c] = act( sum_k A[n,k] * W[c,k] + bias[c] )
// Block tile 128x128, BK=32, 8 warps (2x4), warp tile 64x32.
// ---------------------------------------------------------------------------
template<int K, bool RELU, bool BIAS>
__global__ __launch_bounds__(256) void gemm_tf32(
    const float* __restrict__ A,
    const float* __restrict__ W,
    const float* __restrict__ bias,
    float* __restrict__ out,
    int n_rows)
{
    __shared__ unsigned As[128][36];   // [m][k], pad 4 -> conflict-free frag loads
    __shared__ unsigned Ws[128][36];   // [n][k]

    const int tid  = threadIdx.x;
    const int lane = tid & 31;
    const int warp = tid >> 5;
    const int wm   = warp >> 2;        // 0..1  -> m offset wm*64
    const int wn   = warp & 3;         // 0..3  -> n offset wn*32
    const int g    = lane >> 2;        // 0..7
    const int t    = lane & 3;         // 0..3
    const int row0 = blockIdx.x * 128;

    const int lr = tid >> 3;           // 0..31 (load row, +it*32)
    const int lk = (tid & 7) * 4;      // 0..28 (load k4)

    float c[4][4][4];                  // [mi][ni][reg]
#pragma unroll
    for (int mi = 0; mi < 4; ++mi)
#pragma unroll
        for (int ni = 0; ni < 4; ++ni)
#pragma unroll
            for (int r = 0; r < 4; ++r) c[mi][ni][r] = 0.0f;

    for (int kt = 0; kt < K; kt += 32) {
        // Load A tile 128x32 (row-major, guarded), cvt to tf32
#pragma unroll
        for (int it = 0; it < 4; ++it) {
            int r = lr + it * 32;
            int gr = row0 + r;
            float4 v = make_float4(0.f, 0.f, 0.f, 0.f);
            if (gr < n_rows)
                v = *(const float4*)(A + (size_t)gr * K + kt + lk);
            uint4 u = make_uint4(f2tf(v.x), f2tf(v.y), f2tf(v.z), f2tf(v.w));
            *(uint4*)&As[r][lk] = u;
        }
        // Load W tile 128x32
#pragma unroll
        for (int it = 0; it < 4; ++it) {
            int r = lr + it * 32;
            float4 v = *(const float4*)(W + (size_t)r * K + kt + lk);
            uint4 u = make_uint4(f2tf(v.x), f2tf(v.y), f2tf(v.z), f2tf(v.w));
            *(uint4*)&Ws[r][lk] = u;
        }
        __syncthreads();

#pragma unroll
        for (int kk = 0; kk < 32; kk += 8) {
            unsigned af[4][4], bf[4][2];
#pragma unroll
            for (int mi = 0; mi < 4; ++mi) {
                int m0 = wm * 64 + mi * 16;
                af[mi][0] = As[m0 + g][kk + t];
                af[mi][1] = As[m0 + g + 8][kk + t];
                af[mi][2] = As[m0 + g][kk + t + 4];
                af[mi][3] = As[m0 + g + 8][kk + t + 4];
            }
#pragma unroll
            for (int ni = 0; ni < 4; ++ni) {
                int n0 = wn * 32 + ni * 8;
                bf[ni][0] = Ws[n0 + g][kk + t];
                bf[ni][1] = Ws[n0 + g][kk + t + 4];
            }
#pragma unroll
            for (int mi = 0; mi < 4; ++mi)
#pragma unroll
                for (int ni = 0; ni < 4; ++ni)
                    mma_tf32(c[mi][ni], af[mi][0], af[mi][1], af[mi][2], af[mi][3],
                             bf[ni][0], bf[ni][1]);
        }
        __syncthreads();
    }

    // Epilogue: c0,c1 at (row=g, col=2t,2t+1); c2,c3 at row=g+8
#pragma unroll
    for (int mi = 0; mi < 4; ++mi) {
#pragma unroll
        for (int ni = 0; ni < 4; ++ni) {
            int col = wn * 32 + ni * 8 + 2 * t;
            float b0v = 0.f, b1v = 0.f;
            if (BIAS) { b0v = bias[col]; b1v = bias[col + 1]; }
#pragma unroll
            for (int half = 0; half < 2; ++half) {
                int row = row0 + wm * 64 + mi * 16 + g + half * 8;
                if (row >= n_rows) continue;
                float v0 = c[mi][ni][half * 2 + 0] + b0v;
                float v1 = c[mi][ni][half * 2 + 1] + b1v;
                if (RELU) { v0 = fmaxf(v0, 0.f); v1 = fmaxf(v1, 0.f); }
                float2 o = make_float2(v0, v1);
                *(float2*)(out + (size_t)row * CC + col) = o;
            }
        }
    }
}

// ---------------------------------------------------------------------------
// Degree / CSR construction
// ---------------------------------------------------------------------------
__global__ void zero_kernel() {
    int i = blockIdx.x * blockDim.x + threadIdx.x;
    if (i < NN) { g_cnt[i] = 0; g_cursor[i] = 0; }
}

__global__ void count_kernel(const int* __restrict__ dst) {
    int e = blockIdx.x * blockDim.x + threadIdx.x;
    if (e < EE) atomicAdd(&g_cnt[dst[e]], 1);
}

__global__ void dinv_kernel() {
    int i = blockIdx.x * blockDim.x + threadIdx.x;
    if (i < NN) g_dinv[i] = rsqrtf((float)(g_cnt[i] + 1));
}

// block-wise exclusive scan (1024 threads, Hillis-Steele)
__global__ __launch_bounds__(1024) void scan1_kernel() {
    __shared__ int s[1024];
    int tid = threadIdx.x;
    int i = blockIdx.x * 1024 + tid;
    int v = (i < NN) ? g_cnt[i] : 0;
    s[tid] = v;
    __syncthreads();
#pragma unroll
    for (int off = 1; off < 1024; off <<= 1) {
        int tv = (tid >= off) ? s[tid - off] : 0;
        __syncthreads();
        s[tid] += tv;
        __syncthreads();
    }
    if (i < NN) g_row_start[i] = s[tid] - v;   // exclusive within block
    if (tid == 1023) g_bsum[blockIdx.x] = s[1023];
}

__global__ __launch_bounds__(128) void scan2_kernel() {
    __shared__ int s[128];
    int tid = threadIdx.x;
    int v = (tid < NB1) ? g_bsum[tid] : 0;
    s[tid] = v;
    __syncthreads();
#pragma unroll
    for (int off = 1; off < 128; off <<= 1) {
        int tv = (tid >= off) ? s[tid - off] : 0;
        __syncthreads();
        s[tid] += tv;
        __syncthreads();
    }
    if (tid < NB1) g_bsum[tid] = s[tid] - v;   // exclusive
}

__global__ void scan3_kernel() {
    int i = blockIdx.x * blockDim.x + threadIdx.x;
    if (i < NN) g_row_start[i] += g_bsum[i >> 10];
}

__global__ void fill_kernel(const int* __restrict__ src, const int* __restrict__ dst) {
    int e = blockIdx.x * blockDim.x + threadIdx.x;
    if (e >= EE) return;
    int d = dst[e];
    int pos = g_row_start[d] + atomicAdd(&g_cursor[d], 1);
    g_csr_src[pos] = src[e];
}

// ---------------------------------------------------------------------------
// Gather: one warp per node. out[d] = b2 + z[d]*dinv[d]^2 + sum_e z[s]*dinv[s]*dinv[d]
// ---------------------------------------------------------------------------
__global__ __launch_bounds__(256) void gather_kernel(
    const float* __restrict__ z,
    const float* __restrict__ b2,
    float* __restrict__ out)
{
    int w = (blockIdx.x * blockDim.x + threadIdx.x) >> 5;
    if (w >= NN) return;
    int lane = threadIdx.x & 31;

    int start = g_row_start[w];
    int cnt   = g_cnt[w];
    float dd  = g_dinv[w];

    const float4* zp = (const float4*)z;
    float4 zs = zp[(size_t)w * 32 + lane];
    float4 bv = ((const float4*)b2)[lane];
    float sw = dd * dd;
    float4 acc;
    acc.x = bv.x + zs.x * sw;
    acc.y = bv.y + zs.y * sw;
    acc.z = bv.z + zs.z * sw;
    acc.w = bv.w + zs.w * sw;

    int j = 0;
    for (; j + 2 <= cnt; j += 2) {
        int s0 = g_csr_src[start + j];
        int s1 = g_csr_src[start + j + 1];
        float w0 = g_dinv[s0] * dd;
        float w1 = g_dinv[s1] * dd;
        float4 v0 = zp[(size_t)s0 * 32 + lane];
        float4 v1 = zp[(size_t)s1 * 32 + lane];
        acc.x += v0.x * w0 + v1.x * w1;
        acc.y += v0.y * w0 + v1.y * w1;
        acc.z += v0.z * w0 + v1.z * w1;
        acc.w += v0.w * w0 + v1.w * w1;
    }
    if (j < cnt) {
        int s0 = g_csr_src[start + j];
        float w0 = g_dinv[s0] * dd;
        float4 v0 = zp[(size_t)s0 * 32 + lane];
        acc.x += v0.x * w0;
        acc.y += v0.y * w0;
        acc.z += v0.z * w0;
        acc.w += v0.w * w0;
    }
    ((float4*)out)[(size_t)w * 32 + lane] = acc;
}

// ---------------------------------------------------------------------------
extern "C" void kernel_launch(void* const* d_in, const int* in_sizes, int n_in,
                              void* d_out, int out_size)
{
    const float* x  = (const float*)d_in[0];
    const int*   ei = (const int*)  d_in[1];
    const float* W1 = (const float*)d_in[2];
    const float* b1 = (const float*)d_in[3];
    const float* W2 = (const float*)d_in[4];
    const float* b2 = (const float*)d_in[5];
    float* out = (float*)d_out;

    const int* src = ei;
    const int* dst = ei + EE;

    float* h_ptr; cudaGetSymbolAddress((void**)&h_ptr, g_h);
    float* z_ptr; cudaGetSymbolAddress((void**)&z_ptr, g_z);

    // CSR / degree pipeline
    zero_kernel<<<(NN + 255) / 256, 256>>>();
    count_kernel<<<(EE + 255) / 256, 256>>>(dst);
    dinv_kernel<<<(NN + 255) / 256, 256>>>();
    scan1_kernel<<<NB1, 1024>>>();
    scan2_kernel<<<1, 128>>>();
    scan3_kernel<<<(NN + 255) / 256, 256>>>();
    fill_kernel<<<(EE + 255) / 256, 256>>>(src, dst);

    // GEMMs (TF32 tensor cores)
    gemm_tf32<FIN, true, true ><<<(NN + 127) / 128, 256>>>(x,     W1, b1,      h_ptr, NN);
    gemm_tf32<CC,  false, false><<<(NN + 127) / 128, 256>>>(h_ptr, W2, nullptr, z_ptr, NN);

    // Aggregate
    gather_kernel<<<(NN * 32 + 255) / 256, 256>>>(z_ptr, b2, out);
}